// round 12
// baseline (speedup 1.0000x reference)
#include <cuda_runtime.h>
#include <cuda_fp16.h>
#include <cstdint>

// ---------------- problem constants ----------------
#define BW    1024
#define SEQ   144
#define CH    512
#define NH    16
#define DH    32
#define NWIN  64
#define MROWS (BW*SEQ)          // 147456
#define LOG100 4.6051701859880913680f

// ---------------- scratch ----------------
__device__ __half g_qhi[(size_t)MROWS * 512];
__device__ __half g_qlo[(size_t)MROWS * 512];
__device__ __half g_khi[(size_t)MROWS * 512];
__device__ __half g_klo[(size_t)MROWS * 512];
__device__ __half g_vh [(size_t)MROWS * 512];
__device__ __half g_atth[(size_t)MROWS * 512];
__device__ __half g_xh[(size_t)MROWS * 512];
__device__ __half g_wh[4 * 512 * 512];

// ---------------- helpers ----------------
__device__ __forceinline__ uint32_t pack2h(float x, float y) {
    __half2 h = __floats2half2_rn(x, y);
    return *(uint32_t*)&h;
}
__device__ __forceinline__ float2 unpack2h(uint32_t u) {
    __half2 h = *(__half2*)&u;
    return __half22float2(h);
}
__device__ __forceinline__ uint32_t smem_u32(const void* p) {
    uint32_t a;
    asm("{ .reg .u64 t; cvta.to.shared.u64 t, %1; cvt.u32.u64 %0, t; }" : "=r"(a) : "l"(p));
    return a;
}
__device__ __forceinline__ void mma16(float* c, const uint32_t* a, uint32_t b0, uint32_t b1) {
    asm volatile(
        "mma.sync.aligned.m16n8k16.row.col.f32.f16.f16.f32 "
        "{%0,%1,%2,%3}, {%4,%5,%6,%7}, {%8,%9}, {%0,%1,%2,%3};\n"
        : "+f"(c[0]), "+f"(c[1]), "+f"(c[2]), "+f"(c[3])
        : "r"(a[0]), "r"(a[1]), "r"(a[2]), "r"(a[3]), "r"(b0), "r"(b1));
}
__device__ __forceinline__ void ldsm4(uint32_t& r0, uint32_t& r1, uint32_t& r2, uint32_t& r3,
                                      uint32_t addr) {
    asm volatile("ldmatrix.sync.aligned.m8n8.x4.shared.b16 {%0,%1,%2,%3}, [%4];"
                 : "=r"(r0), "=r"(r1), "=r"(r2), "=r"(r3) : "r"(addr));
}
__device__ __forceinline__ void ldsm4t(uint32_t& r0, uint32_t& r1, uint32_t& r2, uint32_t& r3,
                                       uint32_t addr) {
    asm volatile("ldmatrix.sync.aligned.m8n8.x4.trans.shared.b16 {%0,%1,%2,%3}, [%4];"
                 : "=r"(r0), "=r"(r1), "=r"(r2), "=r"(r3) : "r"(addr));
}
__device__ __forceinline__ void cp16(uint32_t dst, const void* src) {
    asm volatile("cp.async.cg.shared.global [%0], [%1], 16;" :: "r"(dst), "l"(src));
}
__device__ __forceinline__ float qsum(float x) {
    x += __shfl_xor_sync(0xffffffffu, x, 1);
    x += __shfl_xor_sync(0xffffffffu, x, 2);
    return x;
}

// ============================================================
// GEMM (fp16 in): 128 thr, warp 64x64, CTA 128x128, k-chunk 32,
// 3-stage cp.async (fill issued BEFORE mma loop), ldmatrix frags.
// mode 0: fp32 out + bias; mode 1: QKV epilogue (norm/split).
// ============================================================
#define GPAD 20
#define TILE_W (128 * GPAD)
#define GEMM_SMEM (6 * TILE_W * 4)        // 61440 B

__global__ void __launch_bounds__(128, 3)
gemm_h_kernel(const __half* __restrict__ A,
              const __half* __restrict__ B0, const __half* __restrict__ B1,
              const __half* __restrict__ B2,
              const float* __restrict__ bias0, const float* __restrict__ bias1,
              const float* __restrict__ bias2,
              float* __restrict__ Cout, int ldc, int mode,
              const float* __restrict__ ls,
              __half* __restrict__ qhi, __half* __restrict__ qlo,
              __half* __restrict__ khi, __half* __restrict__ klo,
              __half* __restrict__ vh)
{
    const int z  = blockIdx.x >> 2;
    const int nb = blockIdx.x & 3;
    const __half* B   = (z == 0) ? B0 : (z == 1 ? B1 : B2);
    const float* bias = (z == 0) ? bias0 : (z == 1 ? bias1 : bias2);

    const int m0 = blockIdx.y * 128;
    const int n0 = nb * 128;

    extern __shared__ uint32_t smem_u[];
    const uint32_t sb = smem_u32(smem_u);

    const int tid  = threadIdx.x;
    const int warp = tid >> 5, lane = tid & 31;
    const int wm = warp & 1;
    const int wn = warp >> 1;
    const int g  = lane >> 2, tg = lane & 3;

    const __half* Ag = A + (size_t)(m0 + tid) * 512;
    const __half* Bg = B + (size_t)(n0 + tid) * 512;

    const int lr16 = lane & 15, lk2 = lane >> 4;
    const uint32_t a_off = ((wm * 64 + lr16) * GPAD + lk2 * 4) * 4;
    const int br = (lane & 7) + ((lane >> 4) << 3), bk = (lane >> 3) & 1;
    const uint32_t b_off = ((wn * 64 + br) * GPAD + bk * 4) * 4;

    float acc[4][8][4];
#pragma unroll
    for (int i = 0; i < 4; i++)
#pragma unroll
        for (int j = 0; j < 8; j++)
#pragma unroll
            for (int r = 0; r < 4; r++) acc[i][j][r] = 0.f;

#pragma unroll
    for (int s = 0; s < 2; s++) {
        uint32_t ad = sb + (2 * s * TILE_W + tid * GPAD) * 4;
        uint32_t bd = ad + TILE_W * 4;
#pragma unroll
        for (int i = 0; i < 4; i++) {
            cp16(ad + i * 16, Ag + s * 32 + i * 8);
            cp16(bd + i * 16, Bg + s * 32 + i * 8);
        }
        asm volatile("cp.async.commit_group;" ::: "memory");
    }

#pragma unroll 1
    for (int kc = 0; kc < 16; kc++) {
        if (kc < 14)
            asm volatile("cp.async.wait_group 1;" ::: "memory");
        else
            asm volatile("cp.async.wait_group 0;" ::: "memory");
        __syncthreads();

        // fill chunk kc+2 early (stage (kc+2)%3 is distinct from kc, kc+1)
        if (kc + 2 < 16) {
            int fs = kc + 2 - ((kc + 2) / 3) * 3;
            uint32_t ad = sb + (2 * fs * TILE_W + tid * GPAD) * 4;
            uint32_t bd = ad + TILE_W * 4;
#pragma unroll
            for (int i = 0; i < 4; i++) {
                cp16(ad + i * 16, Ag + (kc + 2) * 32 + i * 8);
                cp16(bd + i * 16, Bg + (kc + 2) * 32 + i * 8);
            }
            asm volatile("cp.async.commit_group;" ::: "memory");
        }

        const int st = kc - (kc / 3) * 3;
        const uint32_t abase = sb + 2 * st * TILE_W * 4 + a_off;
        const uint32_t bbase = sb + (2 * st + 1) * TILE_W * 4 + b_off;

#pragma unroll
        for (int T = 0; T < 2; T++) {
            uint32_t af[4][4], bf[4][4];
#pragma unroll
            for (int mi = 0; mi < 4; mi++)
                ldsm4(af[mi][0], af[mi][1], af[mi][2], af[mi][3],
                      abase + (mi * 16 * GPAD + T * 8) * 4);
#pragma unroll
            for (int np = 0; np < 4; np++)
                ldsm4(bf[np][0], bf[np][1], bf[np][2], bf[np][3],
                      bbase + (np * 16 * GPAD + T * 8) * 4);
#pragma unroll
            for (int np = 0; np < 4; np++)
#pragma unroll
                for (int mi = 0; mi < 4; mi++) {
                    mma16(acc[mi][2 * np],     af[mi], bf[np][0], bf[np][1]);
                    mma16(acc[mi][2 * np + 1], af[mi], bf[np][2], bf[np][3]);
                }
        }
    }

    // ---- add bias ----
#pragma unroll
    for (int mi = 0; mi < 4; mi++)
#pragma unroll
        for (int ni = 0; ni < 8; ni++) {
            int ncol = n0 + wn * 64 + ni * 8 + 2 * tg;
            float b0 = bias[ncol], b1 = bias[ncol + 1];
            acc[mi][ni][0] += b0; acc[mi][ni][1] += b1;
            acc[mi][ni][2] += b0; acc[mi][ni][3] += b1;
        }

    if (mode == 0) {
#pragma unroll
        for (int mi = 0; mi < 4; mi++) {
            int row = m0 + wm * 64 + mi * 16 + g;
#pragma unroll
            for (int ni = 0; ni < 8; ni++) {
                int gcol = n0 + wn * 64 + ni * 8 + 2 * tg;
                *(float2*)(Cout + (size_t)row * ldc + gcol) =
                    make_float2(acc[mi][ni][0], acc[mi][ni][1]);
                *(float2*)(Cout + (size_t)(row + 8) * ldc + gcol) =
                    make_float2(acc[mi][ni][2], acc[mi][ni][3]);
            }
        }
        return;
    }

    // ---- mode 1: QKV epilogue ----
    if (z == 2) {   // v: plain fp16
#pragma unroll
        for (int mi = 0; mi < 4; mi++) {
            int row = m0 + wm * 64 + mi * 16 + g;
#pragma unroll
            for (int ni = 0; ni < 8; ni++) {
                int gcol = n0 + wn * 64 + ni * 8 + 2 * tg;
                *(uint32_t*)(vh + (size_t)row * 512 + gcol) =
                    pack2h(acc[mi][ni][0], acc[mi][ni][1]);
                *(uint32_t*)(vh + (size_t)(row + 8) * 512 + gcol) =
                    pack2h(acc[mi][ni][2], acc[mi][ni][3]);
            }
        }
        return;
    }

    __half* dhi = (z == 0) ? qhi : khi;
    __half* dlo = (z == 0) ? qlo : klo;
    float scA = 1.f, scB = 1.f;
    const int hA = (n0 + wn * 64) >> 5;
    if (z == 0) {
        scA = expf(fminf(ls[hA], LOG100));
        scB = expf(fminf(ls[hA + 1], LOG100));
    }

#pragma unroll
    for (int mi = 0; mi < 4; mi++) {
        float sA0 = 0.f, sA1 = 0.f, sB0 = 0.f, sB1 = 0.f;
#pragma unroll
        for (int ni = 0; ni < 4; ni++) {
            sA0 += acc[mi][ni][0] * acc[mi][ni][0] + acc[mi][ni][1] * acc[mi][ni][1];
            sA1 += acc[mi][ni][2] * acc[mi][ni][2] + acc[mi][ni][3] * acc[mi][ni][3];
            sB0 += acc[mi][ni+4][0] * acc[mi][ni+4][0] + acc[mi][ni+4][1] * acc[mi][ni+4][1];
            sB1 += acc[mi][ni+4][2] * acc[mi][ni+4][2] + acc[mi][ni+4][3] * acc[mi][ni+4][3];
        }
        sA0 = qsum(sA0); sA1 = qsum(sA1); sB0 = qsum(sB0); sB1 = qsum(sB1);
        float iA0 = scA / fmaxf(sqrtf(sA0), 1e-12f);
        float iA1 = scA / fmaxf(sqrtf(sA1), 1e-12f);
        float iB0 = scB / fmaxf(sqrtf(sB0), 1e-12f);
        float iB1 = scB / fmaxf(sqrtf(sB1), 1e-12f);

        int row = m0 + wm * 64 + mi * 16 + g;
#pragma unroll
        for (int ni = 0; ni < 8; ni++) {
            float i0 = (ni < 4) ? iA0 : iB0;
            float i1 = (ni < 4) ? iA1 : iB1;
            int gcol = n0 + wn * 64 + ni * 8 + 2 * tg;
            float f0 = acc[mi][ni][0] * i0, f1 = acc[mi][ni][1] * i0;
            uint32_t hi = pack2h(f0, f1);
            float2 hf = unpack2h(hi);
            *(uint32_t*)(dhi + (size_t)row * 512 + gcol) = hi;
            *(uint32_t*)(dlo + (size_t)row * 512 + gcol) = pack2h(f0 - hf.x, f1 - hf.y);
            float f2 = acc[mi][ni][2] * i1, f3 = acc[mi][ni][3] * i1;
            uint32_t hi2 = pack2h(f2, f3);
            float2 hf2 = unpack2h(hi2);
            *(uint32_t*)(dhi + (size_t)(row + 8) * 512 + gcol) = hi2;
            *(uint32_t*)(dlo + (size_t)(row + 8) * 512 + gcol) = pack2h(f2 - hf2.x, f3 - hf2.y);
        }
    }
}

// ============================================================
// conversion kernels
// ============================================================
__global__ void convert_x_kernel(const float* __restrict__ x, __half* __restrict__ o)
{
    size_t i = (size_t)blockIdx.x * 256 + threadIdx.x;
    float4 v = ((const float4*)x)[i];
    ((uint2*)o)[i] = make_uint2(pack2h(v.x, v.y), pack2h(v.z, v.w));
}

__global__ void convert_w_kernel(const float* __restrict__ w0, const float* __restrict__ w1,
                                 const float* __restrict__ w2, const float* __restrict__ w3,
                                 __half* __restrict__ o)
{
    size_t i = (size_t)blockIdx.x * 256 + threadIdx.x;
    const float* srcs[4] = {w0, w1, w2, w3};
#pragma unroll
    for (int m = 0; m < 4; m++) {
        float4 v = ((const float4*)srcs[m])[i];
        ((uint2*)(o + (size_t)m * 262144))[i] = make_uint2(pack2h(v.x, v.y), pack2h(v.z, v.w));
    }
}

// ============================================================
// Attention (fp16 flash): 5 warps x 32 q-rows (mi=2), rows padded
// 144->160 (phantom q=0, stores guarded). 9 strips of 16 keys.
// K/V fragments via ldmatrix serve BOTH m16 tiles (wf/mma 1.25).
// q/k pre-normalized + pre-split by GEMM epilogue; P in registers.
// ============================================================
#define KSP 20
#define ATT_SMEM (3 * 144 * KSP * 4)   // 34560 B

__global__ void __launch_bounds__(160, 3)
attn_kernel(const float* __restrict__ mask,
            const __half* __restrict__ qhi, const __half* __restrict__ qlo,
            const __half* __restrict__ khi, const __half* __restrict__ klo,
            const __half* __restrict__ vh,
            __half* __restrict__ attout)
{
    const int bh = blockIdx.x;
    const int b = bh >> 4;
    const int h = bh & 15;
    const int win = b & (NWIN - 1);

    const int tid = threadIdx.x;
    const int w = tid >> 5, lane = tid & 31;
    const int g = lane >> 2, tg = lane & 3;

    extern __shared__ uint32_t sm_u[];
    const uint32_t sb = smem_u32(sm_u);
    const uint32_t khi_b = sb;
    const uint32_t klo_b = sb + 144 * KSP * 4;
    const uint32_t vs_b  = sb + 2 * 144 * KSP * 4;

    // ---- prologue: copy K hi/lo and V rows (2 uint4 per 16-half seg) ----
#pragma unroll
    for (int t = tid; t < 288; t += 160) {
        const int key = t >> 1, seg = t & 1;
        const size_t off = (size_t)(b * SEQ + key) * 512 + h * 32 + seg * 16;
        uint32_t* dh = sm_u + key * KSP + seg * 8;
        uint32_t* dl = dh + 144 * KSP;
        uint32_t* dv = dh + 2 * 144 * KSP;
        *(uint4*)dh       = *(const uint4*)(khi + off);
        *(uint4*)(dh + 4) = *(const uint4*)(khi + off + 8);
        *(uint4*)dl       = *(const uint4*)(klo + off);
        *(uint4*)(dl + 4) = *(const uint4*)(klo + off + 8);
        *(uint4*)dv       = *(const uint4*)(vh + off);
        *(uint4*)(dv + 4) = *(const uint4*)(vh + off + 8);
    }

    // ---- Q fragments (2 mi tiles) from pre-split global arrays ----
    uint32_t ah[2][2][4], al[2][2][4];
#pragma unroll
    for (int mi = 0; mi < 2; mi++) {
        const int rA = w * 32 + mi * 16 + g, rB = rA + 8;
        const __half* qhA = qhi + (size_t)(b * SEQ + rA) * 512 + h * 32;
        const __half* qhB = qhi + (size_t)(b * SEQ + rB) * 512 + h * 32;
        const __half* qlA = qlo + (size_t)(b * SEQ + rA) * 512 + h * 32;
        const __half* qlB = qlo + (size_t)(b * SEQ + rB) * 512 + h * 32;
        const bool okA = (rA < 144), okB = (rB < 144);
#pragma unroll
        for (int T = 0; T < 2; T++)
#pragma unroll
            for (int p = 0; p < 2; p++) {
                int d = 16 * T + 8 * p + 2 * tg;
                ah[mi][T][2 * p]     = okA ? *(const uint32_t*)(qhA + d) : 0u;
                ah[mi][T][2 * p + 1] = okB ? *(const uint32_t*)(qhB + d) : 0u;
                al[mi][T][2 * p]     = okA ? *(const uint32_t*)(qlA + d) : 0u;
                al[mi][T][2 * p + 1] = okB ? *(const uint32_t*)(qlB + d) : 0u;
            }
    }
    __syncthreads();

    // ldmatrix per-thread offsets
    const int kr8 = (lane & 7) + ((lane >> 4) << 3);
    const int kb  = (lane >> 3) & 1;
    const uint32_t koff = (uint32_t)(kr8 * KSP + kb * 4) * 4;                    // K
    const uint32_t voff = (uint32_t)((lane & 15) * KSP) * 4 + (lane >> 4) * 16;  // V (trans)

    // ---- online softmax state ----
    const float NEG_INF = __int_as_float(0xff800000);
    float mr[2][2] = {{NEG_INF, NEG_INF}, {NEG_INF, NEG_INF}};
    float sr[2][2] = {{0.f, 0.f}, {0.f, 0.f}};
    float oc[2][4][4];
#pragma unroll
    for (int mi = 0; mi < 2; mi++)
#pragma unroll
        for (int nt = 0; nt < 4; nt++)
#pragma unroll
            for (int r = 0; r < 4; r++) oc[mi][nt][r] = 0.f;

    const float* mbase = mask + (size_t)win * SEQ * SEQ + 2 * tg;
    const float* mrow[2][2];
#pragma unroll
    for (int mi = 0; mi < 2; mi++) {
        int rA = w * 32 + mi * 16 + g, rB = rA + 8;
        mrow[mi][0] = mbase + (size_t)(rA < 144 ? rA : 143) * SEQ;
        mrow[mi][1] = mbase + (size_t)(rB < 144 ? rB : 143) * SEQ;
    }

    // ---- 9 strips of 16 keys ----
#pragma unroll 1
    for (int s = 0; s < 9; s++) {
        const int key0 = 16 * s;

        float sacc[2][2][4];
#pragma unroll
        for (int mi = 0; mi < 2; mi++)
#pragma unroll
            for (int nt = 0; nt < 2; nt++)
#pragma unroll
                for (int r = 0; r < 4; r++) sacc[mi][nt][r] = 0.f;

#pragma unroll
        for (int T = 0; T < 2; T++) {
            uint32_t kh[4], kl[4];
            uint32_t base = (uint32_t)(key0 * KSP + T * 8) * 4 + koff;
            ldsm4(kh[0], kh[1], kh[2], kh[3], khi_b + base);
            ldsm4(kl[0], kl[1], kl[2], kl[3], klo_b + base);
#pragma unroll
            for (int mi = 0; mi < 2; mi++) {
                mma16(sacc[mi][0], ah[mi][T], kh[0], kh[1]);
                mma16(sacc[mi][0], al[mi][T], kh[0], kh[1]);
                mma16(sacc[mi][0], ah[mi][T], kl[0], kl[1]);
                mma16(sacc[mi][1], ah[mi][T], kh[2], kh[3]);
                mma16(sacc[mi][1], al[mi][T], kh[2], kh[3]);
                mma16(sacc[mi][1], ah[mi][T], kl[2], kl[3]);
            }
        }

        // masks + online softmax + P pack (per mi)
        uint32_t pa[2][4];
#pragma unroll
        for (int mi = 0; mi < 2; mi++) {
            float2 m00 = *(const float2*)(mrow[mi][0] + key0);
            float2 m01 = *(const float2*)(mrow[mi][0] + key0 + 8);
            float2 m10 = *(const float2*)(mrow[mi][1] + key0);
            float2 m11 = *(const float2*)(mrow[mi][1] + key0 + 8);
            sacc[mi][0][0] += m00.x; sacc[mi][0][1] += m00.y;
            sacc[mi][1][0] += m01.x; sacc[mi][1][1] += m01.y;
            sacc[mi][0][2] += m10.x; sacc[mi][0][3] += m10.y;
            sacc[mi][1][2] += m11.x; sacc[mi][1][3] += m11.y;

            float mx0 = fmaxf(fmaxf(sacc[mi][0][0], sacc[mi][0][1]),
                              fmaxf(sacc[mi][1][0], sacc[mi][1][1]));
            float mx1 = fmaxf(fmaxf(sacc[mi][0][2], sacc[mi][0][3]),
                              fmaxf(sacc[mi][1][2], sacc[mi][1][3]));
            mx0 = fmaxf(mx0, __shfl_xor_sync(0xffffffffu, mx0, 1));
            mx0 = fmaxf(mx0, __shfl_xor_sync(0xffffffffu, mx0, 2));
            mx1 = fmaxf(mx1, __shfl_xor_sync(0xffffffffu, mx1, 1));
            mx1 = fmaxf(mx1, __shfl_xor_sync(0xffffffffu, mx1, 2));

            float mn0 = fmaxf(mr[mi][0], mx0), mn1 = fmaxf(mr[mi][1], mx1);
            float f0 = __expf(mr[mi][0] - mn0), f1 = __expf(mr[mi][1] - mn1);
            mr[mi][0] = mn0; mr[mi][1] = mn1;
            sr[mi][0] *= f0; sr[mi][1] *= f1;
#pragma unroll
            for (int nt = 0; nt < 4; nt++) {
                oc[mi][nt][0] *= f0; oc[mi][nt][1] *= f0;
                oc[mi][nt][2] *= f1; oc[mi][nt][3] *= f1;
            }

            float p00 = __expf(sacc[mi][0][0] - mn0), p01 = __expf(sacc[mi][0][1] - mn0);
            float p02 = __expf(sacc[mi][0][2] - mn1), p03 = __expf(sacc[mi][0][3] - mn1);
            float p10 = __expf(sacc[mi][1][0] - mn0), p11 = __expf(sacc[mi][1][1] - mn0);
            float p12 = __expf(sacc[mi][1][2] - mn1), p13 = __expf(sacc[mi][1][3] - mn1);
            sr[mi][0] += p00 + p01 + p10 + p11;
            sr[mi][1] += p02 + p03 + p12 + p13;
            pa[mi][0] = pack2h(p00, p01);
            pa[mi][1] = pack2h(p02, p03);
            pa[mi][2] = pack2h(p10, p11);
            pa[mi][3] = pack2h(p12, p13);
        }

        // PV: 2 trans-ldmatrix serve both mi tiles
        {
            const uint32_t vbase = vs_b + (uint32_t)(key0 * KSP) * 4 + voff;
            uint32_t vb[4];
            ldsm4t(vb[0], vb[1], vb[2], vb[3], vbase);          // d 0..15
#pragma unroll
            for (int mi = 0; mi < 2; mi++) {
                mma16(oc[mi][0], pa[mi], vb[0], vb[1]);
                mma16(oc[mi][1], pa[mi], vb[2], vb[3]);
            }
            ldsm4t(vb[0], vb[1], vb[2], vb[3], vbase + 32);     // d 16..31
#pragma unroll
            for (int mi = 0; mi < 2; mi++) {
                mma16(oc[mi][2], pa[mi], vb[0], vb[1]);
                mma16(oc[mi][3], pa[mi], vb[2], vb[3]);
            }
        }
    }

    // ---- finalize & store (guard phantom rows) ----
    uint32_t* out32 = (uint32_t*)attout;
#pragma unroll
    for (int mi = 0; mi < 2; mi++) {
        float s0 = qsum(sr[mi][0]);
        float s1 = qsum(sr[mi][1]);
        float inv0 = 1.f / s0, inv1 = 1.f / s1;

        const int rA = w * 32 + mi * 16 + g;
        if (rA < 144) {
            const int row0 = b * SEQ + rA;
#pragma unroll
            for (int nt = 0; nt < 4; nt++) {
                int col = h * 32 + nt * 8 + 2 * tg;
                out32[((size_t)row0 * 512 + col) >> 1] =
                    pack2h(oc[mi][nt][0] * inv0, oc[mi][nt][1] * inv0);
                out32[(((size_t)(row0 + 8)) * 512 + col) >> 1] =
                    pack2h(oc[mi][nt][2] * inv1, oc[mi][nt][3] * inv1);
            }
        }
    }
}

// ============================================================
// launch
// ============================================================
extern "C" void kernel_launch(void* const* d_in, const int* in_sizes, int n_in,
                              void* d_out, int out_size)
{
    (void)in_sizes; (void)n_in; (void)out_size;
    const float* x    = (const float*)d_in[0];
    const float* mask = (const float*)d_in[1];
    const float* Wq   = (const float*)d_in[2];
    const float* bq   = (const float*)d_in[3];
    const float* Wk   = (const float*)d_in[4];
    const float* bk   = (const float*)d_in[5];
    const float* Wv   = (const float*)d_in[6];
    const float* bv   = (const float*)d_in[7];
    const float* Wp   = (const float*)d_in[8];
    const float* bp   = (const float*)d_in[9];
    const float* ls   = (const float*)d_in[10];
    float* out = (float*)d_out;

    void *p0, *p1, *p2, *p3, *p4, *p5, *p6, *p7;
    cudaGetSymbolAddress(&p0, g_qhi);
    cudaGetSymbolAddress(&p1, g_qlo);
    cudaGetSymbolAddress(&p2, g_khi);
    cudaGetSymbolAddress(&p3, g_klo);
    cudaGetSymbolAddress(&p4, g_vh);
    cudaGetSymbolAddress(&p5, g_atth);
    cudaGetSymbolAddress(&p6, g_xh);
    cudaGetSymbolAddress(&p7, g_wh);
    __half* qhi  = (__half*)p0;
    __half* qlo  = (__half*)p1;
    __half* khi  = (__half*)p2;
    __half* klo  = (__half*)p3;
    __half* vh   = (__half*)p4;
    __half* atth = (__half*)p5;
    __half* xh   = (__half*)p6;
    __half* wh   = (__half*)p7;

    cudaFuncSetAttribute(gemm_h_kernel,
                         cudaFuncAttributeMaxDynamicSharedMemorySize, GEMM_SMEM);
    cudaFuncSetAttribute(attn_kernel,
                         cudaFuncAttributeMaxDynamicSharedMemorySize, ATT_SMEM);

    // 0) fp32 -> fp16
    convert_x_kernel<<<MROWS * 512 / 4 / 256, 256>>>(x, xh);
    convert_w_kernel<<<256, 256>>>(Wq, Wk, Wv, Wp, wh);

    // 1) QKV projections (mode 1: normalize/split epilogue)
    gemm_h_kernel<<<dim3(12, MROWS / 128), 128, GEMM_SMEM>>>(
        xh, wh, wh + 262144, wh + 2 * 262144, bq, bk, bv,
        nullptr, 0, 1, ls, qhi, qlo, khi, klo, vh);

    // 2) attention (mi=2, 16-key strips)
    attn_kernel<<<BW * NH, 160, ATT_SMEM>>>(mask, qhi, qlo, khi, klo, vh, atth);

    // 3) output projection (mode 0)
    gemm_h_kernel<<<dim3(4, MROWS / 128), 128, GEMM_SMEM>>>(
        atth, wh + 3 * 262144, wh + 3 * 262144, wh + 3 * 262144, bp, bp, bp,
        out, 512, 0, nullptr, nullptr, nullptr, nullptr, nullptr, nullptr);
}

// round 13
// speedup vs baseline: 1.0744x; 1.0744x over previous
#include <cuda_runtime.h>
#include <cuda_fp16.h>
#include <cstdint>

// ---------------- problem constants ----------------
#define BW    1024
#define SEQ   144
#define CH    512
#define NH    16
#define DH    32
#define NWIN  64
#define MROWS (BW*SEQ)          // 147456
#define LOG100 4.6051701859880913680f

// ---------------- scratch ----------------
__device__ __half g_qhi[(size_t)MROWS * 512];
__device__ __half g_qlo[(size_t)MROWS * 512];
__device__ __half g_khi[(size_t)MROWS * 512];
__device__ __half g_klo[(size_t)MROWS * 512];
__device__ __half g_vh [(size_t)MROWS * 512];
__device__ __half g_atth[(size_t)MROWS * 512];
__device__ __half g_xh[(size_t)MROWS * 512];
__device__ __half g_wh[4 * 512 * 512];
__device__ __half g_maskh[(size_t)NWIN * SEQ * SEQ];

// ---------------- helpers ----------------
__device__ __forceinline__ uint32_t pack2h(float x, float y) {
    __half2 h = __floats2half2_rn(x, y);
    return *(uint32_t*)&h;
}
__device__ __forceinline__ float2 unpack2h(uint32_t u) {
    __half2 h = *(__half2*)&u;
    return __half22float2(h);
}
__device__ __forceinline__ uint32_t smem_u32(const void* p) {
    uint32_t a;
    asm("{ .reg .u64 t; cvta.to.shared.u64 t, %1; cvt.u32.u64 %0, t; }" : "=r"(a) : "l"(p));
    return a;
}
__device__ __forceinline__ void mma16(float* c, const uint32_t* a, uint32_t b0, uint32_t b1) {
    asm volatile(
        "mma.sync.aligned.m16n8k16.row.col.f32.f16.f16.f32 "
        "{%0,%1,%2,%3}, {%4,%5,%6,%7}, {%8,%9}, {%0,%1,%2,%3};\n"
        : "+f"(c[0]), "+f"(c[1]), "+f"(c[2]), "+f"(c[3])
        : "r"(a[0]), "r"(a[1]), "r"(a[2]), "r"(a[3]), "r"(b0), "r"(b1));
}
__device__ __forceinline__ void ldsm4(uint32_t& r0, uint32_t& r1, uint32_t& r2, uint32_t& r3,
                                      uint32_t addr) {
    asm volatile("ldmatrix.sync.aligned.m8n8.x4.shared.b16 {%0,%1,%2,%3}, [%4];"
                 : "=r"(r0), "=r"(r1), "=r"(r2), "=r"(r3) : "r"(addr));
}
__device__ __forceinline__ void ldsm4t(uint32_t& r0, uint32_t& r1, uint32_t& r2, uint32_t& r3,
                                       uint32_t addr) {
    asm volatile("ldmatrix.sync.aligned.m8n8.x4.trans.shared.b16 {%0,%1,%2,%3}, [%4];"
                 : "=r"(r0), "=r"(r1), "=r"(r2), "=r"(r3) : "r"(addr));
}
__device__ __forceinline__ void cp16(uint32_t dst, const void* src) {
    asm volatile("cp.async.cg.shared.global [%0], [%1], 16;" :: "r"(dst), "l"(src));
}
__device__ __forceinline__ float qsum(float x) {
    x += __shfl_xor_sync(0xffffffffu, x, 1);
    x += __shfl_xor_sync(0xffffffffu, x, 2);
    return x;
}

// ============================================================
// GEMM (fp16 in): 128 thr, warp 64x64, CTA 128x128, k-chunk 32,
// 3-stage cp.async, ldmatrix frags. Fill AFTER compute (r11 order:
// cp.asyncs must not precede the critical ldmatrix in the L1tex FIFO).
// mode 0: fp32 out + bias; mode 1: QKV epilogue (norm/split).
// ============================================================
#define GPAD 20
#define TILE_W (128 * GPAD)
#define GEMM_SMEM (6 * TILE_W * 4)        // 61440 B

__global__ void __launch_bounds__(128, 3)
gemm_h_kernel(const __half* __restrict__ A,
              const __half* __restrict__ B0, const __half* __restrict__ B1,
              const __half* __restrict__ B2,
              const float* __restrict__ bias0, const float* __restrict__ bias1,
              const float* __restrict__ bias2,
              float* __restrict__ Cout, int ldc, int mode,
              const float* __restrict__ ls,
              __half* __restrict__ qhi, __half* __restrict__ qlo,
              __half* __restrict__ khi, __half* __restrict__ klo,
              __half* __restrict__ vh)
{
    const int z  = blockIdx.x >> 2;
    const int nb = blockIdx.x & 3;
    const __half* B   = (z == 0) ? B0 : (z == 1 ? B1 : B2);
    const float* bias = (z == 0) ? bias0 : (z == 1 ? bias1 : bias2);

    const int m0 = blockIdx.y * 128;
    const int n0 = nb * 128;

    extern __shared__ uint32_t smem_u[];
    const uint32_t sb = smem_u32(smem_u);

    const int tid  = threadIdx.x;
    const int warp = tid >> 5, lane = tid & 31;
    const int wm = warp & 1;
    const int wn = warp >> 1;
    const int g  = lane >> 2, tg = lane & 3;

    const __half* Ag = A + (size_t)(m0 + tid) * 512;
    const __half* Bg = B + (size_t)(n0 + tid) * 512;

    const int lr16 = lane & 15, lk2 = lane >> 4;
    const uint32_t a_off = ((wm * 64 + lr16) * GPAD + lk2 * 4) * 4;
    const int br = (lane & 7) + ((lane >> 4) << 3), bk = (lane >> 3) & 1;
    const uint32_t b_off = ((wn * 64 + br) * GPAD + bk * 4) * 4;

    float acc[4][8][4];
#pragma unroll
    for (int i = 0; i < 4; i++)
#pragma unroll
        for (int j = 0; j < 8; j++)
#pragma unroll
            for (int r = 0; r < 4; r++) acc[i][j][r] = 0.f;

#pragma unroll
    for (int s = 0; s < 2; s++) {
        uint32_t ad = sb + (2 * s * TILE_W + tid * GPAD) * 4;
        uint32_t bd = ad + TILE_W * 4;
#pragma unroll
        for (int i = 0; i < 4; i++) {
            cp16(ad + i * 16, Ag + s * 32 + i * 8);
            cp16(bd + i * 16, Bg + s * 32 + i * 8);
        }
        asm volatile("cp.async.commit_group;" ::: "memory");
    }

#pragma unroll 1
    for (int kc = 0; kc < 16; kc++) {
        if (kc < 14)
            asm volatile("cp.async.wait_group 1;" ::: "memory");
        else
            asm volatile("cp.async.wait_group 0;" ::: "memory");
        __syncthreads();

        const int st = kc - (kc / 3) * 3;
        const uint32_t abase = sb + 2 * st * TILE_W * 4 + a_off;
        const uint32_t bbase = sb + (2 * st + 1) * TILE_W * 4 + b_off;

#pragma unroll
        for (int T = 0; T < 2; T++) {
            uint32_t af[4][4], bf[4][4];
#pragma unroll
            for (int mi = 0; mi < 4; mi++)
                ldsm4(af[mi][0], af[mi][1], af[mi][2], af[mi][3],
                      abase + (mi * 16 * GPAD + T * 8) * 4);
#pragma unroll
            for (int np = 0; np < 4; np++)
                ldsm4(bf[np][0], bf[np][1], bf[np][2], bf[np][3],
                      bbase + (np * 16 * GPAD + T * 8) * 4);
#pragma unroll
            for (int np = 0; np < 4; np++)
#pragma unroll
                for (int mi = 0; mi < 4; mi++) {
                    mma16(acc[mi][2 * np],     af[mi], bf[np][0], bf[np][1]);
                    mma16(acc[mi][2 * np + 1], af[mi], bf[np][2], bf[np][3]);
                }
        }

        // fill chunk kc+2 AFTER compute (keeps ldmatrix ahead in L1tex queue)
        if (kc + 2 < 16) {
            int fs = kc + 2 - ((kc + 2) / 3) * 3;
            uint32_t ad = sb + (2 * fs * TILE_W + tid * GPAD) * 4;
            uint32_t bd = ad + TILE_W * 4;
#pragma unroll
            for (int i = 0; i < 4; i++) {
                cp16(ad + i * 16, Ag + (kc + 2) * 32 + i * 8);
                cp16(bd + i * 16, Bg + (kc + 2) * 32 + i * 8);
            }
            asm volatile("cp.async.commit_group;" ::: "memory");
        }
    }

    // ---- add bias ----
#pragma unroll
    for (int mi = 0; mi < 4; mi++)
#pragma unroll
        for (int ni = 0; ni < 8; ni++) {
            int ncol = n0 + wn * 64 + ni * 8 + 2 * tg;
            float b0 = bias[ncol], b1 = bias[ncol + 1];
            acc[mi][ni][0] += b0; acc[mi][ni][1] += b1;
            acc[mi][ni][2] += b0; acc[mi][ni][3] += b1;
        }

    if (mode == 0) {
#pragma unroll
        for (int mi = 0; mi < 4; mi++) {
            int row = m0 + wm * 64 + mi * 16 + g;
#pragma unroll
            for (int ni = 0; ni < 8; ni++) {
                int gcol = n0 + wn * 64 + ni * 8 + 2 * tg;
                *(float2*)(Cout + (size_t)row * ldc + gcol) =
                    make_float2(acc[mi][ni][0], acc[mi][ni][1]);
                *(float2*)(Cout + (size_t)(row + 8) * ldc + gcol) =
                    make_float2(acc[mi][ni][2], acc[mi][ni][3]);
            }
        }
        return;
    }

    // ---- mode 1: QKV epilogue ----
    if (z == 2) {   // v: plain fp16
#pragma unroll
        for (int mi = 0; mi < 4; mi++) {
            int row = m0 + wm * 64 + mi * 16 + g;
#pragma unroll
            for (int ni = 0; ni < 8; ni++) {
                int gcol = n0 + wn * 64 + ni * 8 + 2 * tg;
                *(uint32_t*)(vh + (size_t)row * 512 + gcol) =
                    pack2h(acc[mi][ni][0], acc[mi][ni][1]);
                *(uint32_t*)(vh + (size_t)(row + 8) * 512 + gcol) =
                    pack2h(acc[mi][ni][2], acc[mi][ni][3]);
            }
        }
        return;
    }

    __half* dhi = (z == 0) ? qhi : khi;
    __half* dlo = (z == 0) ? qlo : klo;
    float scA = 1.f, scB = 1.f;
    const int hA = (n0 + wn * 64) >> 5;
    if (z == 0) {
        scA = expf(fminf(ls[hA], LOG100));
        scB = expf(fminf(ls[hA + 1], LOG100));
    }

#pragma unroll
    for (int mi = 0; mi < 4; mi++) {
        float sA0 = 0.f, sA1 = 0.f, sB0 = 0.f, sB1 = 0.f;
#pragma unroll
        for (int ni = 0; ni < 4; ni++) {
            sA0 += acc[mi][ni][0] * acc[mi][ni][0] + acc[mi][ni][1] * acc[mi][ni][1];
            sA1 += acc[mi][ni][2] * acc[mi][ni][2] + acc[mi][ni][3] * acc[mi][ni][3];
            sB0 += acc[mi][ni+4][0] * acc[mi][ni+4][0] + acc[mi][ni+4][1] * acc[mi][ni+4][1];
            sB1 += acc[mi][ni+4][2] * acc[mi][ni+4][2] + acc[mi][ni+4][3] * acc[mi][ni+4][3];
        }
        sA0 = qsum(sA0); sA1 = qsum(sA1); sB0 = qsum(sB0); sB1 = qsum(sB1);
        float iA0 = scA / fmaxf(sqrtf(sA0), 1e-12f);
        float iA1 = scA / fmaxf(sqrtf(sA1), 1e-12f);
        float iB0 = scB / fmaxf(sqrtf(sB0), 1e-12f);
        float iB1 = scB / fmaxf(sqrtf(sB1), 1e-12f);

        int row = m0 + wm * 64 + mi * 16 + g;
#pragma unroll
        for (int ni = 0; ni < 8; ni++) {
            float i0 = (ni < 4) ? iA0 : iB0;
            float i1 = (ni < 4) ? iA1 : iB1;
            int gcol = n0 + wn * 64 + ni * 8 + 2 * tg;
            float f0 = acc[mi][ni][0] * i0, f1 = acc[mi][ni][1] * i0;
            uint32_t hi = pack2h(f0, f1);
            float2 hf = unpack2h(hi);
            *(uint32_t*)(dhi + (size_t)row * 512 + gcol) = hi;
            *(uint32_t*)(dlo + (size_t)row * 512 + gcol) = pack2h(f0 - hf.x, f1 - hf.y);
            float f2 = acc[mi][ni][2] * i1, f3 = acc[mi][ni][3] * i1;
            uint32_t hi2 = pack2h(f2, f3);
            float2 hf2 = unpack2h(hi2);
            *(uint32_t*)(dhi + (size_t)(row + 8) * 512 + gcol) = hi2;
            *(uint32_t*)(dlo + (size_t)(row + 8) * 512 + gcol) = pack2h(f2 - hf2.x, f3 - hf2.y);
        }
    }
}

// ============================================================
// conversion kernels
// ============================================================
__global__ void convert_x_kernel(const float* __restrict__ x, __half* __restrict__ o)
{
    size_t i = (size_t)blockIdx.x * 256 + threadIdx.x;
    float4 v = ((const float4*)x)[i];
    ((uint2*)o)[i] = make_uint2(pack2h(v.x, v.y), pack2h(v.z, v.w));
}

__global__ void convert_w_kernel(const float* __restrict__ w0, const float* __restrict__ w1,
                                 const float* __restrict__ w2, const float* __restrict__ w3,
                                 __half* __restrict__ o)
{
    size_t i = (size_t)blockIdx.x * 256 + threadIdx.x;
    const float* srcs[4] = {w0, w1, w2, w3};
#pragma unroll
    for (int m = 0; m < 4; m++) {
        float4 v = ((const float4*)srcs[m])[i];
        ((uint2*)(o + (size_t)m * 262144))[i] = make_uint2(pack2h(v.x, v.y), pack2h(v.z, v.w));
    }
}

__global__ void convert_mask_kernel(const float* __restrict__ m, __half* __restrict__ o)
{
    size_t i = (size_t)blockIdx.x * 256 + threadIdx.x;   // 331776 float4s
    float4 v = ((const float4*)m)[i];
    ((uint2*)o)[i] = make_uint2(pack2h(v.x, v.y), pack2h(v.z, v.w));
}

// ============================================================
// Attention (fp16 flash): 5 warps x 32 q-rows (mi=2), rows padded
// 144->160 (phantom q=0, stores guarded). 9 strips of 16 keys.
// K/V fragments via ldmatrix serve BOTH m16 tiles. fp16 mask.
// q/k pre-normalized + pre-split by GEMM epilogue; P in registers.
// ============================================================
#define KSP 20
#define ATT_SMEM (3 * 144 * KSP * 4)   // 34560 B

__global__ void __launch_bounds__(160, 3)
attn_kernel(const __half* __restrict__ maskh,
            const __half* __restrict__ qhi, const __half* __restrict__ qlo,
            const __half* __restrict__ khi, const __half* __restrict__ klo,
            const __half* __restrict__ vh,
            __half* __restrict__ attout)
{
    const int bh = blockIdx.x;
    const int b = bh >> 4;
    const int h = bh & 15;
    const int win = b & (NWIN - 1);

    const int tid = threadIdx.x;
    const int w = tid >> 5, lane = tid & 31;
    const int g = lane >> 2, tg = lane & 3;

    extern __shared__ uint32_t sm_u[];
    const uint32_t sb = smem_u32(sm_u);
    const uint32_t khi_b = sb;
    const uint32_t klo_b = sb + 144 * KSP * 4;
    const uint32_t vs_b  = sb + 2 * 144 * KSP * 4;

    // ---- prologue: copy K hi/lo and V rows (2 uint4 per 16-half seg) ----
#pragma unroll
    for (int t = tid; t < 288; t += 160) {
        const int key = t >> 1, seg = t & 1;
        const size_t off = (size_t)(b * SEQ + key) * 512 + h * 32 + seg * 16;
        uint32_t* dh = sm_u + key * KSP + seg * 8;
        uint32_t* dl = dh + 144 * KSP;
        uint32_t* dv = dh + 2 * 144 * KSP;
        *(uint4*)dh       = *(const uint4*)(khi + off);
        *(uint4*)(dh + 4) = *(const uint4*)(khi + off + 8);
        *(uint4*)dl       = *(const uint4*)(klo + off);
        *(uint4*)(dl + 4) = *(const uint4*)(klo + off + 8);
        *(uint4*)dv       = *(const uint4*)(vh + off);
        *(uint4*)(dv + 4) = *(const uint4*)(vh + off + 8);
    }

    // ---- Q fragments (2 mi tiles) from pre-split global arrays ----
    uint32_t ah[2][2][4], al[2][2][4];
#pragma unroll
    for (int mi = 0; mi < 2; mi++) {
        const int rA = w * 32 + mi * 16 + g, rB = rA + 8;
        const __half* qhA = qhi + (size_t)(b * SEQ + rA) * 512 + h * 32;
        const __half* qhB = qhi + (size_t)(b * SEQ + rB) * 512 + h * 32;
        const __half* qlA = qlo + (size_t)(b * SEQ + rA) * 512 + h * 32;
        const __half* qlB = qlo + (size_t)(b * SEQ + rB) * 512 + h * 32;
        const bool okA = (rA < 144), okB = (rB < 144);
#pragma unroll
        for (int T = 0; T < 2; T++)
#pragma unroll
            for (int p = 0; p < 2; p++) {
                int d = 16 * T + 8 * p + 2 * tg;
                ah[mi][T][2 * p]     = okA ? *(const uint32_t*)(qhA + d) : 0u;
                ah[mi][T][2 * p + 1] = okB ? *(const uint32_t*)(qhB + d) : 0u;
                al[mi][T][2 * p]     = okA ? *(const uint32_t*)(qlA + d) : 0u;
                al[mi][T][2 * p + 1] = okB ? *(const uint32_t*)(qlB + d) : 0u;
            }
    }
    __syncthreads();

    // ldmatrix per-thread offsets
    const int kr8 = (lane & 7) + ((lane >> 4) << 3);
    const int kb  = (lane >> 3) & 1;
    const uint32_t koff = (uint32_t)(kr8 * KSP + kb * 4) * 4;                    // K
    const uint32_t voff = (uint32_t)((lane & 15) * KSP) * 4 + (lane >> 4) * 16;  // V (trans)

    // ---- online softmax state ----
    const float NEG_INF = __int_as_float(0xff800000);
    float mr[2][2] = {{NEG_INF, NEG_INF}, {NEG_INF, NEG_INF}};
    float sr[2][2] = {{0.f, 0.f}, {0.f, 0.f}};
    float oc[2][4][4];
#pragma unroll
    for (int mi = 0; mi < 2; mi++)
#pragma unroll
        for (int nt = 0; nt < 4; nt++)
#pragma unroll
            for (int r = 0; r < 4; r++) oc[mi][nt][r] = 0.f;

    const __half* mbase = maskh + (size_t)win * SEQ * SEQ + 2 * tg;
    const __half* mrow[2][2];
#pragma unroll
    for (int mi = 0; mi < 2; mi++) {
        int rA = w * 32 + mi * 16 + g, rB = rA + 8;
        mrow[mi][0] = mbase + (size_t)(rA < 144 ? rA : 143) * SEQ;
        mrow[mi][1] = mbase + (size_t)(rB < 144 ? rB : 143) * SEQ;
    }

    // ---- 9 strips of 16 keys ----
#pragma unroll 1
    for (int s = 0; s < 9; s++) {
        const int key0 = 16 * s;

        float sacc[2][2][4];
#pragma unroll
        for (int mi = 0; mi < 2; mi++)
#pragma unroll
            for (int nt = 0; nt < 2; nt++)
#pragma unroll
                for (int r = 0; r < 4; r++) sacc[mi][nt][r] = 0.f;

#pragma unroll
        for (int T = 0; T < 2; T++) {
            uint32_t kh[4], kl[4];
            uint32_t base = (uint32_t)(key0 * KSP + T * 8) * 4 + koff;
            ldsm4(kh[0], kh[1], kh[2], kh[3], khi_b + base);
            ldsm4(kl[0], kl[1], kl[2], kl[3], klo_b + base);
#pragma unroll
            for (int mi = 0; mi < 2; mi++) {
                mma16(sacc[mi][0], ah[mi][T], kh[0], kh[1]);
                mma16(sacc[mi][0], al[mi][T], kh[0], kh[1]);
                mma16(sacc[mi][0], ah[mi][T], kl[0], kl[1]);
                mma16(sacc[mi][1], ah[mi][T], kh[2], kh[3]);
                mma16(sacc[mi][1], al[mi][T], kh[2], kh[3]);
                mma16(sacc[mi][1], ah[mi][T], kl[2], kl[3]);
            }
        }

        // masks (fp16) + online softmax + P pack (per mi)
        uint32_t pa[2][4];
#pragma unroll
        for (int mi = 0; mi < 2; mi++) {
            float2 m00 = unpack2h(*(const uint32_t*)(mrow[mi][0] + key0));
            float2 m01 = unpack2h(*(const uint32_t*)(mrow[mi][0] + key0 + 8));
            float2 m10 = unpack2h(*(const uint32_t*)(mrow[mi][1] + key0));
            float2 m11 = unpack2h(*(const uint32_t*)(mrow[mi][1] + key0 + 8));
            sacc[mi][0][0] += m00.x; sacc[mi][0][1] += m00.y;
            sacc[mi][1][0] += m01.x; sacc[mi][1][1] += m01.y;
            sacc[mi][0][2] += m10.x; sacc[mi][0][3] += m10.y;
            sacc[mi][1][2] += m11.x; sacc[mi][1][3] += m11.y;

            float mx0 = fmaxf(fmaxf(sacc[mi][0][0], sacc[mi][0][1]),
                              fmaxf(sacc[mi][1][0], sacc[mi][1][1]));
            float mx1 = fmaxf(fmaxf(sacc[mi][0][2], sacc[mi][0][3]),
                              fmaxf(sacc[mi][1][2], sacc[mi][1][3]));
            mx0 = fmaxf(mx0, __shfl_xor_sync(0xffffffffu, mx0, 1));
            mx0 = fmaxf(mx0, __shfl_xor_sync(0xffffffffu, mx0, 2));
            mx1 = fmaxf(mx1, __shfl_xor_sync(0xffffffffu, mx1, 1));
            mx1 = fmaxf(mx1, __shfl_xor_sync(0xffffffffu, mx1, 2));

            float mn0 = fmaxf(mr[mi][0], mx0), mn1 = fmaxf(mr[mi][1], mx1);
            float f0 = __expf(mr[mi][0] - mn0), f1 = __expf(mr[mi][1] - mn1);
            mr[mi][0] = mn0; mr[mi][1] = mn1;
            sr[mi][0] *= f0; sr[mi][1] *= f1;
#pragma unroll
            for (int nt = 0; nt < 4; nt++) {
                oc[mi][nt][0] *= f0; oc[mi][nt][1] *= f0;
                oc[mi][nt][2] *= f1; oc[mi][nt][3] *= f1;
            }

            float p00 = __expf(sacc[mi][0][0] - mn0), p01 = __expf(sacc[mi][0][1] - mn0);
            float p02 = __expf(sacc[mi][0][2] - mn1), p03 = __expf(sacc[mi][0][3] - mn1);
            float p10 = __expf(sacc[mi][1][0] - mn0), p11 = __expf(sacc[mi][1][1] - mn0);
            float p12 = __expf(sacc[mi][1][2] - mn1), p13 = __expf(sacc[mi][1][3] - mn1);
            sr[mi][0] += p00 + p01 + p10 + p11;
            sr[mi][1] += p02 + p03 + p12 + p13;
            pa[mi][0] = pack2h(p00, p01);
            pa[mi][1] = pack2h(p02, p03);
            pa[mi][2] = pack2h(p10, p11);
            pa[mi][3] = pack2h(p12, p13);
        }

        // PV: 2 trans-ldmatrix serve both mi tiles
        {
            const uint32_t vbase = vs_b + (uint32_t)(key0 * KSP) * 4 + voff;
            uint32_t vb[4];
            ldsm4t(vb[0], vb[1], vb[2], vb[3], vbase);          // d 0..15
#pragma unroll
            for (int mi = 0; mi < 2; mi++) {
                mma16(oc[mi][0], pa[mi], vb[0], vb[1]);
                mma16(oc[mi][1], pa[mi], vb[2], vb[3]);
            }
            ldsm4t(vb[0], vb[1], vb[2], vb[3], vbase + 32);     // d 16..31
#pragma unroll
            for (int mi = 0; mi < 2; mi++) {
                mma16(oc[mi][2], pa[mi], vb[0], vb[1]);
                mma16(oc[mi][3], pa[mi], vb[2], vb[3]);
            }
        }
    }

    // ---- finalize & store (guard phantom rows) ----
    uint32_t* out32 = (uint32_t*)attout;
#pragma unroll
    for (int mi = 0; mi < 2; mi++) {
        float s0 = qsum(sr[mi][0]);
        float s1 = qsum(sr[mi][1]);
        float inv0 = 1.f / s0, inv1 = 1.f / s1;

        const int rA = w * 32 + mi * 16 + g;
        if (rA < 144) {
            const int row0 = b * SEQ + rA;
#pragma unroll
            for (int nt = 0; nt < 4; nt++) {
                int col = h * 32 + nt * 8 + 2 * tg;
                out32[((size_t)row0 * 512 + col) >> 1] =
                    pack2h(oc[mi][nt][0] * inv0, oc[mi][nt][1] * inv0);
                out32[(((size_t)(row0 + 8)) * 512 + col) >> 1] =
                    pack2h(oc[mi][nt][2] * inv1, oc[mi][nt][3] * inv1);
            }
        }
    }
}

// ============================================================
// launch
// ============================================================
extern "C" void kernel_launch(void* const* d_in, const int* in_sizes, int n_in,
                              void* d_out, int out_size)
{
    (void)in_sizes; (void)n_in; (void)out_size;
    const float* x    = (const float*)d_in[0];
    const float* mask = (const float*)d_in[1];
    const float* Wq   = (const float*)d_in[2];
    const float* bq   = (const float*)d_in[3];
    const float* Wk   = (const float*)d_in[4];
    const float* bk   = (const float*)d_in[5];
    const float* Wv   = (const float*)d_in[6];
    const float* bv   = (const float*)d_in[7];
    const float* Wp   = (const float*)d_in[8];
    const float* bp   = (const float*)d_in[9];
    const float* ls   = (const float*)d_in[10];
    float* out = (float*)d_out;

    void *p0, *p1, *p2, *p3, *p4, *p5, *p6, *p7, *p8;
    cudaGetSymbolAddress(&p0, g_qhi);
    cudaGetSymbolAddress(&p1, g_qlo);
    cudaGetSymbolAddress(&p2, g_khi);
    cudaGetSymbolAddress(&p3, g_klo);
    cudaGetSymbolAddress(&p4, g_vh);
    cudaGetSymbolAddress(&p5, g_atth);
    cudaGetSymbolAddress(&p6, g_xh);
    cudaGetSymbolAddress(&p7, g_wh);
    cudaGetSymbolAddress(&p8, g_maskh);
    __half* qhi   = (__half*)p0;
    __half* qlo   = (__half*)p1;
    __half* khi   = (__half*)p2;
    __half* klo   = (__half*)p3;
    __half* vh    = (__half*)p4;
    __half* atth  = (__half*)p5;
    __half* xh    = (__half*)p6;
    __half* wh    = (__half*)p7;
    __half* maskh = (__half*)p8;

    cudaFuncSetAttribute(gemm_h_kernel,
                         cudaFuncAttributeMaxDynamicSharedMemorySize, GEMM_SMEM);
    cudaFuncSetAttribute(attn_kernel,
                         cudaFuncAttributeMaxDynamicSharedMemorySize, ATT_SMEM);

    // 0) fp32 -> fp16 conversions
    convert_x_kernel<<<MROWS * 512 / 4 / 256, 256>>>(x, xh);
    convert_w_kernel<<<256, 256>>>(Wq, Wk, Wv, Wp, wh);
    convert_mask_kernel<<<NWIN * SEQ * SEQ / 4 / 256, 256>>>(mask, maskh);

    // 1) QKV projections (mode 1: normalize/split epilogue)
    gemm_h_kernel<<<dim3(12, MROWS / 128), 128, GEMM_SMEM>>>(
        xh, wh, wh + 262144, wh + 2 * 262144, bq, bk, bv,
        nullptr, 0, 1, ls, qhi, qlo, khi, klo, vh);

    // 2) attention (mi=2, 16-key strips, fp16 mask)
    attn_kernel<<<BW * NH, 160, ATT_SMEM>>>(maskh, qhi, qlo, khi, klo, vh, atth);

    // 3) output projection (mode 0)
    gemm_h_kernel<<<dim3(4, MROWS / 128), 128, GEMM_SMEM>>>(
        atth, wh + 3 * 262144, wh + 3 * 262144, wh + 3 * 262144, bp, bp, bp,
        out, 512, 0, nullptr, nullptr, nullptr, nullptr, nullptr, nullptr);
}

// round 14
// speedup vs baseline: 1.0874x; 1.0120x over previous
#include <cuda_runtime.h>
#include <cuda_fp16.h>
#include <cstdint>

// ---------------- problem constants ----------------
#define BW    1024
#define SEQ   144
#define CH    512
#define NH    16
#define DH    32
#define NWIN  64
#define MROWS (BW*SEQ)          // 147456
#define LOG100 4.6051701859880913680f

// ---------------- scratch ----------------
__device__ __half g_qhi[(size_t)MROWS * 512];
__device__ __half g_qlo[(size_t)MROWS * 512];
__device__ __half g_khi[(size_t)MROWS * 512];
__device__ __half g_klo[(size_t)MROWS * 512];
__device__ __half g_vh [(size_t)MROWS * 512];
__device__ __half g_atth[(size_t)MROWS * 512];
__device__ __half g_xh[(size_t)MROWS * 512];
__device__ __half g_wh[4 * 512 * 512];
__device__ __half g_maskh[(size_t)NWIN * SEQ * SEQ];

// ---------------- helpers ----------------
__device__ __forceinline__ uint32_t pack2h(float x, float y) {
    __half2 h = __floats2half2_rn(x, y);
    return *(uint32_t*)&h;
}
__device__ __forceinline__ float2 unpack2h(uint32_t u) {
    __half2 h = *(__half2*)&u;
    return __half22float2(h);
}
__device__ __forceinline__ uint32_t smem_u32(const void* p) {
    uint32_t a;
    asm("{ .reg .u64 t; cvta.to.shared.u64 t, %1; cvt.u32.u64 %0, t; }" : "=r"(a) : "l"(p));
    return a;
}
__device__ __forceinline__ void mma16(float* c, const uint32_t* a, uint32_t b0, uint32_t b1) {
    asm volatile(
        "mma.sync.aligned.m16n8k16.row.col.f32.f16.f16.f32 "
        "{%0,%1,%2,%3}, {%4,%5,%6,%7}, {%8,%9}, {%0,%1,%2,%3};\n"
        : "+f"(c[0]), "+f"(c[1]), "+f"(c[2]), "+f"(c[3])
        : "r"(a[0]), "r"(a[1]), "r"(a[2]), "r"(a[3]), "r"(b0), "r"(b1));
}
__device__ __forceinline__ void ldsm4(uint32_t& r0, uint32_t& r1, uint32_t& r2, uint32_t& r3,
                                      uint32_t addr) {
    asm volatile("ldmatrix.sync.aligned.m8n8.x4.shared.b16 {%0,%1,%2,%3}, [%4];"
                 : "=r"(r0), "=r"(r1), "=r"(r2), "=r"(r3) : "r"(addr));
}
__device__ __forceinline__ void ldsm4t(uint32_t& r0, uint32_t& r1, uint32_t& r2, uint32_t& r3,
                                       uint32_t addr) {
    asm volatile("ldmatrix.sync.aligned.m8n8.x4.trans.shared.b16 {%0,%1,%2,%3}, [%4];"
                 : "=r"(r0), "=r"(r1), "=r"(r2), "=r"(r3) : "r"(addr));
}
__device__ __forceinline__ void cp16(uint32_t dst, const void* src) {
    asm volatile("cp.async.cg.shared.global [%0], [%1], 16;" :: "r"(dst), "l"(src));
}
__device__ __forceinline__ float qsum(float x) {
    x += __shfl_xor_sync(0xffffffffu, x, 1);
    x += __shfl_xor_sync(0xffffffffu, x, 2);
    return x;
}

// ============================================================
// Persistent-B GEMM: each CTA owns one (n-tile, z) weight slice
// (128x512 fp16 = 130KB in smem, loaded once) and streams m-tiles.
// 256 threads, 8 warps (2M x 4N), warp tile 64x32, k-chunk 32,
// 3-stage cp.async A pipeline, flattened (m,k) iteration.
// mode 0: fp32 out + bias; mode 1: QKV epilogue (norm/split).
// ============================================================
#define GPAD 20                          // A stage row stride (words)
#define BST  260                         // B row stride (words): 260%32=4 -> conflict-free
#define A_STAGE_W (128 * GPAD)           // 2560 words
#define PG_SMEM ((128 * BST + 3 * A_STAGE_W) * 4)   // 163840 B

__global__ void __launch_bounds__(256, 1)
pgemm_kernel(const __half* __restrict__ A,
             const __half* __restrict__ B0, const __half* __restrict__ B1,
             const __half* __restrict__ B2,
             const float* __restrict__ bias0, const float* __restrict__ bias1,
             const float* __restrict__ bias2,
             float* __restrict__ Cout, int ldc, int mode,
             const float* __restrict__ ls,
             __half* __restrict__ qhi, __half* __restrict__ qlo,
             __half* __restrict__ khi, __half* __restrict__ klo,
             __half* __restrict__ vh)
{
    const int tile = blockIdx.x;
    const int by   = blockIdx.y;
    const int G    = gridDim.y;
    const int z  = tile >> 2;
    const int nb = tile & 3;
    const __half* B   = (z == 0) ? B0 : (z == 1 ? B1 : B2);
    const float* bias = (z == 0) ? bias0 : (z == 1 ? bias1 : bias2);
    const int n0 = nb * 128;

    extern __shared__ uint32_t smem_u[];
    const uint32_t sb   = smem_u32(smem_u);
    const uint32_t sbA  = sb + 128 * BST * 4;

    const int tid  = threadIdx.x;
    const int warp = tid >> 5, lane = tid & 31;
    const int wm = warp & 1;          // M half (64 rows of 128)
    const int wn = warp >> 1;         // N quarter (32 cols of 128)
    const int g  = lane >> 2, tg = lane & 3;

    // ---- one-time B load (cp.async, 256 halfs per thread) ----
    {
        const int r = tid >> 1, part = tid & 1;
        const __half* src = B + (size_t)(n0 + r) * 512 + part * 256;
        uint32_t dst = sb + (r * BST + part * 128) * 4;
#pragma unroll
        for (int i = 0; i < 32; i++)
            cp16(dst + i * 16, src + i * 8);
        asm volatile("cp.async.commit_group;" ::: "memory");
        asm volatile("cp.async.wait_group 0;" ::: "memory");
    }
    __syncthreads();

    // ldmatrix per-thread offsets
    const int lr16 = lane & 15, lk2 = lane >> 4;
    const uint32_t a_off = (uint32_t)((wm * 64 + lr16) * GPAD + lk2 * 4) * 4;
    const int b_row = (lane & 7) + ((lane >> 4) << 3);
    const int kb = (lane >> 3) & 1;
    const uint32_t b_base = sb + (uint32_t)((wn * 32 + b_row) * BST) * 4 + kb * 16;

    // per-CTA head scale (mode 1, z==0): warp's 32 cols = one head
    float sc = 1.f;
    if (mode == 1 && z == 0)
        sc = expf(fminf(ls[(n0 + wn * 32) >> 5], LOG100));

    // iteration count
    const int nm = (1152 - by + G - 1) / G;
    const int total = nm * 16;

    // prologue: chunks 0,1
#pragma unroll
    for (int p = 0; p < 2; p++) {
        const int r = tid >> 1, part = tid & 1;
        const int m0p = (by) << 7;   // chunks 0,1 are m-tile 0 (kc=0,1)
        const __half* src = A + (size_t)(m0p + r) * 512 + p * 32 + part * 16;
        uint32_t dst = sbA + (uint32_t)(p * A_STAGE_W + r * GPAD + part * 8) * 4;
        cp16(dst, src);
        cp16(dst + 16, src + 8);
        asm volatile("cp.async.commit_group;" ::: "memory");
    }

    float acc[4][4][4];
#pragma unroll
    for (int i = 0; i < 4; i++)
#pragma unroll
        for (int jj = 0; jj < 4; jj++)
#pragma unroll
            for (int r = 0; r < 4; r++) acc[i][jj][r] = 0.f;

#pragma unroll 1
    for (int j = 0; j < total; j++) {
        if (j < total - 2)
            asm volatile("cp.async.wait_group 1;" ::: "memory");
        else
            asm volatile("cp.async.wait_group 0;" ::: "memory");
        __syncthreads();

        const int kc = j & 15;
        const int st = j - (j / 3) * 3;
        const uint32_t abase = sbA + (uint32_t)(st * A_STAGE_W) * 4 + a_off;

#pragma unroll
        for (int T = 0; T < 2; T++) {
            uint32_t af[4][4], bf[2][4];
#pragma unroll
            for (int mi = 0; mi < 4; mi++)
                ldsm4(af[mi][0], af[mi][1], af[mi][2], af[mi][3],
                      abase + (uint32_t)(mi * 16 * GPAD + T * 8) * 4);
#pragma unroll
            for (int nq = 0; nq < 2; nq++)
                ldsm4(bf[nq][0], bf[nq][1], bf[nq][2], bf[nq][3],
                      b_base + (uint32_t)(nq * 16 * BST) * 4
                             + (uint32_t)(kc * 32 + T * 16) * 2);
#pragma unroll
            for (int nq = 0; nq < 2; nq++)
#pragma unroll
                for (int p = 0; p < 2; p++) {
                    uint32_t b0 = bf[nq][2 * p], b1 = bf[nq][2 * p + 1];
#pragma unroll
                    for (int mi = 0; mi < 4; mi++)
                        mma16(acc[mi][nq * 2 + p], af[mi], b0, b1);
                }
        }

        // prefetch chunk j+2
        if (j + 2 < total) {
            const int jn = j + 2;
            const int fs = jn - (jn / 3) * 3;
            const int m0p = (by + (jn >> 4) * G) << 7;
            const int kcp = jn & 15;
            const int r = tid >> 1, part = tid & 1;
            const __half* src = A + (size_t)(m0p + r) * 512 + kcp * 32 + part * 16;
            uint32_t dst = sbA + (uint32_t)(fs * A_STAGE_W + r * GPAD + part * 8) * 4;
            cp16(dst, src);
            cp16(dst + 16, src + 8);
            asm volatile("cp.async.commit_group;" ::: "memory");
        }

        // ---- epilogue at end of each m-tile ----
        if (kc == 15) {
            const int m0 = (by + (j >> 4) * G) << 7;

            // add bias
#pragma unroll
            for (int mi = 0; mi < 4; mi++)
#pragma unroll
                for (int ni = 0; ni < 4; ni++) {
                    int ncol = n0 + wn * 32 + ni * 8 + 2 * tg;
                    float b0v = bias[ncol], b1v = bias[ncol + 1];
                    acc[mi][ni][0] += b0v; acc[mi][ni][1] += b1v;
                    acc[mi][ni][2] += b0v; acc[mi][ni][3] += b1v;
                }

            if (mode == 0) {
#pragma unroll
                for (int mi = 0; mi < 4; mi++) {
                    int row = m0 + wm * 64 + mi * 16 + g;
#pragma unroll
                    for (int ni = 0; ni < 4; ni++) {
                        int gcol = n0 + wn * 32 + ni * 8 + 2 * tg;
                        *(float2*)(Cout + (size_t)row * ldc + gcol) =
                            make_float2(acc[mi][ni][0], acc[mi][ni][1]);
                        *(float2*)(Cout + (size_t)(row + 8) * ldc + gcol) =
                            make_float2(acc[mi][ni][2], acc[mi][ni][3]);
                    }
                }
            } else if (z == 2) {      // v: plain fp16
#pragma unroll
                for (int mi = 0; mi < 4; mi++) {
                    int row = m0 + wm * 64 + mi * 16 + g;
#pragma unroll
                    for (int ni = 0; ni < 4; ni++) {
                        int gcol = n0 + wn * 32 + ni * 8 + 2 * tg;
                        *(uint32_t*)(vh + (size_t)row * 512 + gcol) =
                            pack2h(acc[mi][ni][0], acc[mi][ni][1]);
                        *(uint32_t*)(vh + (size_t)(row + 8) * 512 + gcol) =
                            pack2h(acc[mi][ni][2], acc[mi][ni][3]);
                    }
                }
            } else {                  // q or k: per-head norm + hi/lo split
                __half* dhi = (z == 0) ? qhi : khi;
                __half* dlo = (z == 0) ? qlo : klo;
#pragma unroll
                for (int mi = 0; mi < 4; mi++) {
                    float s0 = 0.f, s1 = 0.f;
#pragma unroll
                    for (int ni = 0; ni < 4; ni++) {
                        s0 += acc[mi][ni][0] * acc[mi][ni][0] + acc[mi][ni][1] * acc[mi][ni][1];
                        s1 += acc[mi][ni][2] * acc[mi][ni][2] + acc[mi][ni][3] * acc[mi][ni][3];
                    }
                    s0 = qsum(s0); s1 = qsum(s1);
                    float i0 = sc / fmaxf(sqrtf(s0), 1e-12f);
                    float i1 = sc / fmaxf(sqrtf(s1), 1e-12f);

                    int row = m0 + wm * 64 + mi * 16 + g;
#pragma unroll
                    for (int ni = 0; ni < 4; ni++) {
                        int gcol = n0 + wn * 32 + ni * 8 + 2 * tg;
                        float f0 = acc[mi][ni][0] * i0, f1 = acc[mi][ni][1] * i0;
                        uint32_t hi = pack2h(f0, f1);
                        float2 hf = unpack2h(hi);
                        *(uint32_t*)(dhi + (size_t)row * 512 + gcol) = hi;
                        *(uint32_t*)(dlo + (size_t)row * 512 + gcol) =
                            pack2h(f0 - hf.x, f1 - hf.y);
                        float f2 = acc[mi][ni][2] * i1, f3 = acc[mi][ni][3] * i1;
                        uint32_t hi2 = pack2h(f2, f3);
                        float2 hf2 = unpack2h(hi2);
                        *(uint32_t*)(dhi + (size_t)(row + 8) * 512 + gcol) = hi2;
                        *(uint32_t*)(dlo + (size_t)(row + 8) * 512 + gcol) =
                            pack2h(f2 - hf2.x, f3 - hf2.y);
                    }
                }
            }

            // reset acc for next m-tile
#pragma unroll
            for (int i = 0; i < 4; i++)
#pragma unroll
                for (int jj = 0; jj < 4; jj++)
#pragma unroll
                    for (int r = 0; r < 4; r++) acc[i][jj][r] = 0.f;
        }
    }
}

// ============================================================
// conversion kernels
// ============================================================
__global__ void convert_x_kernel(const float* __restrict__ x, __half* __restrict__ o)
{
    size_t i = (size_t)blockIdx.x * 256 + threadIdx.x;
    float4 v = ((const float4*)x)[i];
    ((uint2*)o)[i] = make_uint2(pack2h(v.x, v.y), pack2h(v.z, v.w));
}

__global__ void convert_w_kernel(const float* __restrict__ w0, const float* __restrict__ w1,
                                 const float* __restrict__ w2, const float* __restrict__ w3,
                                 __half* __restrict__ o)
{
    size_t i = (size_t)blockIdx.x * 256 + threadIdx.x;
    const float* srcs[4] = {w0, w1, w2, w3};
#pragma unroll
    for (int m = 0; m < 4; m++) {
        float4 v = ((const float4*)srcs[m])[i];
        ((uint2*)(o + (size_t)m * 262144))[i] = make_uint2(pack2h(v.x, v.y), pack2h(v.z, v.w));
    }
}

__global__ void convert_mask_kernel(const float* __restrict__ m, __half* __restrict__ o)
{
    size_t i = (size_t)blockIdx.x * 256 + threadIdx.x;
    float4 v = ((const float4*)m)[i];
    ((uint2*)o)[i] = make_uint2(pack2h(v.x, v.y), pack2h(v.z, v.w));
}

// ============================================================
// Attention (fp16 flash): unchanged from round 13.
// ============================================================
#define KSP 20
#define ATT_SMEM (3 * 144 * KSP * 4)   // 34560 B

__global__ void __launch_bounds__(160, 3)
attn_kernel(const __half* __restrict__ maskh,
            const __half* __restrict__ qhi, const __half* __restrict__ qlo,
            const __half* __restrict__ khi, const __half* __restrict__ klo,
            const __half* __restrict__ vh,
            __half* __restrict__ attout)
{
    const int bh = blockIdx.x;
    const int b = bh >> 4;
    const int h = bh & 15;
    const int win = b & (NWIN - 1);

    const int tid = threadIdx.x;
    const int w = tid >> 5, lane = tid & 31;
    const int g = lane >> 2, tg = lane & 3;

    extern __shared__ uint32_t sm_u[];
    const uint32_t sb = smem_u32(sm_u);
    const uint32_t khi_b = sb;
    const uint32_t klo_b = sb + 144 * KSP * 4;
    const uint32_t vs_b  = sb + 2 * 144 * KSP * 4;

#pragma unroll
    for (int t = tid; t < 288; t += 160) {
        const int key = t >> 1, seg = t & 1;
        const size_t off = (size_t)(b * SEQ + key) * 512 + h * 32 + seg * 16;
        uint32_t* dh = sm_u + key * KSP + seg * 8;
        uint32_t* dl = dh + 144 * KSP;
        uint32_t* dv = dh + 2 * 144 * KSP;
        *(uint4*)dh       = *(const uint4*)(khi + off);
        *(uint4*)(dh + 4) = *(const uint4*)(khi + off + 8);
        *(uint4*)dl       = *(const uint4*)(klo + off);
        *(uint4*)(dl + 4) = *(const uint4*)(klo + off + 8);
        *(uint4*)dv       = *(const uint4*)(vh + off);
        *(uint4*)(dv + 4) = *(const uint4*)(vh + off + 8);
    }

    uint32_t ah[2][2][4], al[2][2][4];
#pragma unroll
    for (int mi = 0; mi < 2; mi++) {
        const int rA = w * 32 + mi * 16 + g, rB = rA + 8;
        const __half* qhA = qhi + (size_t)(b * SEQ + rA) * 512 + h * 32;
        const __half* qhB = qhi + (size_t)(b * SEQ + rB) * 512 + h * 32;
        const __half* qlA = qlo + (size_t)(b * SEQ + rA) * 512 + h * 32;
        const __half* qlB = qlo + (size_t)(b * SEQ + rB) * 512 + h * 32;
        const bool okA = (rA < 144), okB = (rB < 144);
#pragma unroll
        for (int T = 0; T < 2; T++)
#pragma unroll
            for (int p = 0; p < 2; p++) {
                int d = 16 * T + 8 * p + 2 * tg;
                ah[mi][T][2 * p]     = okA ? *(const uint32_t*)(qhA + d) : 0u;
                ah[mi][T][2 * p + 1] = okB ? *(const uint32_t*)(qhB + d) : 0u;
                al[mi][T][2 * p]     = okA ? *(const uint32_t*)(qlA + d) : 0u;
                al[mi][T][2 * p + 1] = okB ? *(const uint32_t*)(qlB + d) : 0u;
            }
    }
    __syncthreads();

    const int kr8 = (lane & 7) + ((lane >> 4) << 3);
    const int kb  = (lane >> 3) & 1;
    const uint32_t koff = (uint32_t)(kr8 * KSP + kb * 4) * 4;
    const uint32_t voff = (uint32_t)((lane & 15) * KSP) * 4 + (lane >> 4) * 16;

    const float NEG_INF = __int_as_float(0xff800000);
    float mr[2][2] = {{NEG_INF, NEG_INF}, {NEG_INF, NEG_INF}};
    float sr[2][2] = {{0.f, 0.f}, {0.f, 0.f}};
    float oc[2][4][4];
#pragma unroll
    for (int mi = 0; mi < 2; mi++)
#pragma unroll
        for (int nt = 0; nt < 4; nt++)
#pragma unroll
            for (int r = 0; r < 4; r++) oc[mi][nt][r] = 0.f;

    const __half* mbase = maskh + (size_t)win * SEQ * SEQ + 2 * tg;
    const __half* mrow[2][2];
#pragma unroll
    for (int mi = 0; mi < 2; mi++) {
        int rA = w * 32 + mi * 16 + g, rB = rA + 8;
        mrow[mi][0] = mbase + (size_t)(rA < 144 ? rA : 143) * SEQ;
        mrow[mi][1] = mbase + (size_t)(rB < 144 ? rB : 143) * SEQ;
    }

#pragma unroll 1
    for (int s = 0; s < 9; s++) {
        const int key0 = 16 * s;

        float sacc[2][2][4];
#pragma unroll
        for (int mi = 0; mi < 2; mi++)
#pragma unroll
            for (int nt = 0; nt < 2; nt++)
#pragma unroll
                for (int r = 0; r < 4; r++) sacc[mi][nt][r] = 0.f;

#pragma unroll
        for (int T = 0; T < 2; T++) {
            uint32_t kh[4], kl[4];
            uint32_t base = (uint32_t)(key0 * KSP + T * 8) * 4 + koff;
            ldsm4(kh[0], kh[1], kh[2], kh[3], khi_b + base);
            ldsm4(kl[0], kl[1], kl[2], kl[3], klo_b + base);
#pragma unroll
            for (int mi = 0; mi < 2; mi++) {
                mma16(sacc[mi][0], ah[mi][T], kh[0], kh[1]);
                mma16(sacc[mi][0], al[mi][T], kh[0], kh[1]);
                mma16(sacc[mi][0], ah[mi][T], kl[0], kl[1]);
                mma16(sacc[mi][1], ah[mi][T], kh[2], kh[3]);
                mma16(sacc[mi][1], al[mi][T], kh[2], kh[3]);
                mma16(sacc[mi][1], ah[mi][T], kl[2], kl[3]);
            }
        }

        uint32_t pa[2][4];
#pragma unroll
        for (int mi = 0; mi < 2; mi++) {
            float2 m00 = unpack2h(*(const uint32_t*)(mrow[mi][0] + key0));
            float2 m01 = unpack2h(*(const uint32_t*)(mrow[mi][0] + key0 + 8));
            float2 m10 = unpack2h(*(const uint32_t*)(mrow[mi][1] + key0));
            float2 m11 = unpack2h(*(const uint32_t*)(mrow[mi][1] + key0 + 8));
            sacc[mi][0][0] += m00.x; sacc[mi][0][1] += m00.y;
            sacc[mi][1][0] += m01.x; sacc[mi][1][1] += m01.y;
            sacc[mi][0][2] += m10.x; sacc[mi][0][3] += m10.y;
            sacc[mi][1][2] += m11.x; sacc[mi][1][3] += m11.y;

            float mx0 = fmaxf(fmaxf(sacc[mi][0][0], sacc[mi][0][1]),
                              fmaxf(sacc[mi][1][0], sacc[mi][1][1]));
            float mx1 = fmaxf(fmaxf(sacc[mi][0][2], sacc[mi][0][3]),
                              fmaxf(sacc[mi][1][2], sacc[mi][1][3]));
            mx0 = fmaxf(mx0, __shfl_xor_sync(0xffffffffu, mx0, 1));
            mx0 = fmaxf(mx0, __shfl_xor_sync(0xffffffffu, mx0, 2));
            mx1 = fmaxf(mx1, __shfl_xor_sync(0xffffffffu, mx1, 1));
            mx1 = fmaxf(mx1, __shfl_xor_sync(0xffffffffu, mx1, 2));

            float mn0 = fmaxf(mr[mi][0], mx0), mn1 = fmaxf(mr[mi][1], mx1);
            float f0 = __expf(mr[mi][0] - mn0), f1 = __expf(mr[mi][1] - mn1);
            mr[mi][0] = mn0; mr[mi][1] = mn1;
            sr[mi][0] *= f0; sr[mi][1] *= f1;
#pragma unroll
            for (int nt = 0; nt < 4; nt++) {
                oc[mi][nt][0] *= f0; oc[mi][nt][1] *= f0;
                oc[mi][nt][2] *= f1; oc[mi][nt][3] *= f1;
            }

            float p00 = __expf(sacc[mi][0][0] - mn0), p01 = __expf(sacc[mi][0][1] - mn0);
            float p02 = __expf(sacc[mi][0][2] - mn1), p03 = __expf(sacc[mi][0][3] - mn1);
            float p10 = __expf(sacc[mi][1][0] - mn0), p11 = __expf(sacc[mi][1][1] - mn0);
            float p12 = __expf(sacc[mi][1][2] - mn1), p13 = __expf(sacc[mi][1][3] - mn1);
            sr[mi][0] += p00 + p01 + p10 + p11;
            sr[mi][1] += p02 + p03 + p12 + p13;
            pa[mi][0] = pack2h(p00, p01);
            pa[mi][1] = pack2h(p02, p03);
            pa[mi][2] = pack2h(p10, p11);
            pa[mi][3] = pack2h(p12, p13);
        }

        {
            const uint32_t vbase = vs_b + (uint32_t)(key0 * KSP) * 4 + voff;
            uint32_t vb[4];
            ldsm4t(vb[0], vb[1], vb[2], vb[3], vbase);
#pragma unroll
            for (int mi = 0; mi < 2; mi++) {
                mma16(oc[mi][0], pa[mi], vb[0], vb[1]);
                mma16(oc[mi][1], pa[mi], vb[2], vb[3]);
            }
            ldsm4t(vb[0], vb[1], vb[2], vb[3], vbase + 32);
#pragma unroll
            for (int mi = 0; mi < 2; mi++) {
                mma16(oc[mi][2], pa[mi], vb[0], vb[1]);
                mma16(oc[mi][3], pa[mi], vb[2], vb[3]);
            }
        }
    }

    uint32_t* out32 = (uint32_t*)attout;
#pragma unroll
    for (int mi = 0; mi < 2; mi++) {
        float s0 = qsum(sr[mi][0]);
        float s1 = qsum(sr[mi][1]);
        float inv0 = 1.f / s0, inv1 = 1.f / s1;

        const int rA = w * 32 + mi * 16 + g;
        if (rA < 144) {
            const int row0 = b * SEQ + rA;
#pragma unroll
            for (int nt = 0; nt < 4; nt++) {
                int col = h * 32 + nt * 8 + 2 * tg;
                out32[((size_t)row0 * 512 + col) >> 1] =
                    pack2h(oc[mi][nt][0] * inv0, oc[mi][nt][1] * inv0);
                out32[(((size_t)(row0 + 8)) * 512 + col) >> 1] =
                    pack2h(oc[mi][nt][2] * inv1, oc[mi][nt][3] * inv1);
            }
        }
    }
}

// ============================================================
// launch
// ============================================================
extern "C" void kernel_launch(void* const* d_in, const int* in_sizes, int n_in,
                              void* d_out, int out_size)
{
    (void)in_sizes; (void)n_in; (void)out_size;
    const float* x    = (const float*)d_in[0];
    const float* mask = (const float*)d_in[1];
    const float* Wq   = (const float*)d_in[2];
    const float* bq   = (const float*)d_in[3];
    const float* Wk   = (const float*)d_in[4];
    const float* bk   = (const float*)d_in[5];
    const float* Wv   = (const float*)d_in[6];
    const float* bv   = (const float*)d_in[7];
    const float* Wp   = (const float*)d_in[8];
    const float* bp   = (const float*)d_in[9];
    const float* ls   = (const float*)d_in[10];
    float* out = (float*)d_out;

    void *p0, *p1, *p2, *p3, *p4, *p5, *p6, *p7, *p8;
    cudaGetSymbolAddress(&p0, g_qhi);
    cudaGetSymbolAddress(&p1, g_qlo);
    cudaGetSymbolAddress(&p2, g_khi);
    cudaGetSymbolAddress(&p3, g_klo);
    cudaGetSymbolAddress(&p4, g_vh);
    cudaGetSymbolAddress(&p5, g_atth);
    cudaGetSymbolAddress(&p6, g_xh);
    cudaGetSymbolAddress(&p7, g_wh);
    cudaGetSymbolAddress(&p8, g_maskh);
    __half* qhi   = (__half*)p0;
    __half* qlo   = (__half*)p1;
    __half* khi   = (__half*)p2;
    __half* klo   = (__half*)p3;
    __half* vh    = (__half*)p4;
    __half* atth  = (__half*)p5;
    __half* xh    = (__half*)p6;
    __half* wh    = (__half*)p7;
    __half* maskh = (__half*)p8;

    cudaFuncSetAttribute(pgemm_kernel,
                         cudaFuncAttributeMaxDynamicSharedMemorySize, PG_SMEM);
    cudaFuncSetAttribute(attn_kernel,
                         cudaFuncAttributeMaxDynamicSharedMemorySize, ATT_SMEM);

    // 0) fp32 -> fp16 conversions
    convert_x_kernel<<<MROWS * 512 / 4 / 256, 256>>>(x, xh);
    convert_w_kernel<<<256, 256>>>(Wq, Wk, Wv, Wp, wh);
    convert_mask_kernel<<<NWIN * SEQ * SEQ / 4 / 256, 256>>>(mask, maskh);

    // 1) QKV projections (persistent-B, mode 1): 12 tiles x 12 CTAs = 144
    pgemm_kernel<<<dim3(12, 12), 256, PG_SMEM>>>(
        xh, wh, wh + 262144, wh + 2 * 262144, bq, bk, bv,
        nullptr, 0, 1, ls, qhi, qlo, khi, klo, vh);

    // 2) attention (unchanged from round 13)
    attn_kernel<<<BW * NH, 160, ATT_SMEM>>>(maskh, qhi, qlo, khi, klo, vh, atth);

    // 3) output projection (persistent-B, mode 0): 4 tiles x 37 CTAs = 148
    pgemm_kernel<<<dim3(4, 37), 256, PG_SMEM>>>(
        atth, wh + 3 * 262144, wh + 3 * 262144, wh + 3 * 262144, bp, bp, bp,
        out, 512, 0, nullptr, nullptr, nullptr, nullptr, nullptr, nullptr);
}